// round 4
// baseline (speedup 1.0000x reference)
#include <cuda_runtime.h>
#include <cuda_bf16.h>

#define N_NODES 50000
#define IN_CH   256
#define HID     128
#define OUT_CH  1000
#define TEXT_DIM 768
#define N_EDGES 800000

// ---------------- scratch (static device arrays; no allocation APIs) --------
__device__ __align__(16) float g_dinv[N_NODES];
__device__ __align__(16) float g_tmp[N_NODES * HID];
__device__ __align__(16) float g_h1 [N_NODES * HID];
__device__ __align__(16) float g_h2 [N_NODES * HID];
__device__ __align__(16) float g_tvec[OUT_CH];

// ---------------- degree / normalization ------------------------------------
__global__ void deg_init_kernel(float* __restrict__ dinv) {
    int i = blockIdx.x * blockDim.x + threadIdx.x;
    if (i < N_NODES) dinv[i] = 1.0f;              // self-loop contributes 1
}

__global__ void deg_count_kernel(const int* __restrict__ dst,
                                 float* __restrict__ dinv) {
    int e = blockIdx.x * blockDim.x + threadIdx.x;
    if (e < N_EDGES) atomicAdd(&dinv[dst[e]], 1.0f);
}

__global__ void deg_rsqrt_kernel(float* __restrict__ dinv) {
    int i = blockIdx.x * blockDim.x + threadIdx.x;
    if (i < N_NODES) dinv[i] = rsqrtf(dinv[i]);   // deg >= 1 always
}

// ---------------- tiled fp32 GEMM: C[N,M] = A[N,K] @ B[K,M] (+addvec) -------
// ADDVEC: 0 = none, 1 = C += addvec[col] after accumulation
template<int BM, int BN, int BK, int TM, int TN, int ADDVEC>
__global__ void __launch_bounds__(256, 2)
gemm_kernel(const float* __restrict__ A, const float* __restrict__ B,
            const float* __restrict__ addvec, float* __restrict__ C,
            int N, int K, int M)
{
    __shared__ float As[BM][BK];
    __shared__ float Bs[BK][BN];

    const int tx = threadIdx.x % (BN / TN);
    const int ty = threadIdx.x / (BN / TN);
    const int rowBase = blockIdx.y * BM;
    const int colBase = blockIdx.x * BN;

    float acc[TM][TN];
#pragma unroll
    for (int i = 0; i < TM; i++)
#pragma unroll
        for (int j = 0; j < TN; j++) acc[i][j] = 0.0f;

    for (int k0 = 0; k0 < K; k0 += BK) {
        for (int i = threadIdx.x; i < BM * BK; i += 256) {
            int r = i / BK, c = i % BK;
            int gr = rowBase + r;
            As[r][c] = (gr < N) ? A[gr * K + k0 + c] : 0.0f;
        }
        for (int i = threadIdx.x; i < BK * BN; i += 256) {
            int r = i / BN, c = i % BN;
            int gc = colBase + c;
            Bs[r][c] = (gc < M) ? B[(k0 + r) * M + gc] : 0.0f;
        }
        __syncthreads();

#pragma unroll
        for (int k = 0; k < BK; k++) {
            float a[TM], b[TN];
#pragma unroll
            for (int i = 0; i < TM; i++) a[i] = As[ty * TM + i][k];
#pragma unroll
            for (int j = 0; j < TN; j++) b[j] = Bs[k][tx * TN + j];
#pragma unroll
            for (int i = 0; i < TM; i++)
#pragma unroll
                for (int j = 0; j < TN; j++) acc[i][j] += a[i] * b[j];
        }
        __syncthreads();
    }

#pragma unroll
    for (int i = 0; i < TM; i++) {
        int gr = rowBase + ty * TM + i;
        if (gr >= N) continue;
#pragma unroll
        for (int j = 0; j < TN; j++) {
            int gc = colBase + tx * TN + j;
            if (gc < M) {
                float v = acc[i][j];
                if (ADDVEC) v += addvec[gc];
                C[gr * M + gc] = v;
            }
        }
    }
}

// ---------------- self-loop init: out = tmp * dinv[node]^2 ------------------
__global__ void self_scale_kernel(const float4* __restrict__ tmp,
                                  const float* __restrict__ dinv,
                                  float4* __restrict__ outv)
{
    int gid = blockIdx.x * blockDim.x + threadIdx.x;       // N_NODES*32 float4
    if (gid >= N_NODES * (HID / 4)) return;
    int node = gid >> 5;
    float w = dinv[node]; w = w * w;
    float4 v = tmp[gid];
    outv[gid] = make_float4(v.x * w, v.y * w, v.z * w, v.w * w);
}

// ---------------- edge aggregation: one warp per edge -----------------------
__global__ void edge_agg_kernel(const int* __restrict__ src,
                                const int* __restrict__ dst,
                                const float* __restrict__ dinv,
                                const float4* __restrict__ h,
                                float* __restrict__ outp)
{
    int gid  = blockIdx.x * blockDim.x + threadIdx.x;
    int warp = gid >> 5;
    int lane = gid & 31;
    if (warp >= N_EDGES) return;
    int s = src[warp];
    int d = dst[warp];
    float w = dinv[s] * dinv[d];
    float4 v = h[s * (HID / 4) + lane];
    float* o = outp + d * HID + lane * 4;
    atomicAdd(o + 0, v.x * w);
    atomicAdd(o + 1, v.y * w);
    atomicAdd(o + 2, v.z * w);
    atomicAdd(o + 3, v.w * w);
}

// ---------------- bias (+optional relu), in place ---------------------------
template<bool RELU>
__global__ void bias_act_kernel(float4* __restrict__ h, const float4* __restrict__ bias)
{
    int gid = blockIdx.x * blockDim.x + threadIdx.x;
    if (gid >= N_NODES * (HID / 4)) return;
    float4 v = h[gid];
    float4 b = bias[gid & ((HID / 4) - 1)];
    v.x += b.x; v.y += b.y; v.z += b.z; v.w += b.w;
    if (RELU) {
        v.x = fmaxf(v.x, 0.f); v.y = fmaxf(v.y, 0.f);
        v.z = fmaxf(v.z, 0.f); v.w = fmaxf(v.w, 0.f);
    }
    h[gid] = v;
}

// ---------------- text_vec @ Wc[HID:, :] + bc -> tvec[OUT_CH] ---------------
__global__ void tvec_kernel(const float* __restrict__ text,
                            const float* __restrict__ Wc,
                            const float* __restrict__ bc,
                            float* __restrict__ tvec)
{
    int j = blockIdx.x * blockDim.x + threadIdx.x;
    if (j >= OUT_CH) return;
    float acc = bc[j];
    for (int k = 0; k < TEXT_DIM; k++)
        acc += text[k] * Wc[(HID + k) * OUT_CH + j];
    tvec[j] = acc;
}

// ---------------------------------------------------------------------------
extern "C" void kernel_launch(void* const* d_in, const int* in_sizes, int n_in,
                              void* d_out, int out_size)
{
    const float* x    = (const float*)d_in[0];
    const int*   ei   = (const int*)d_in[1];       // [2, E] int32 (JAX x64 off)
    const float* text = (const float*)d_in[2];
    const float* W1   = (const float*)d_in[3];
    const float* b1   = (const float*)d_in[4];
    const float* W2   = (const float*)d_in[5];
    const float* b2   = (const float*)d_in[6];
    const float* Wc   = (const float*)d_in[7];
    const float* bc   = (const float*)d_in[8];
    float*       out  = (float*)d_out;

    const int* src = ei;                 // row 0
    const int* dst = ei + N_EDGES;       // row 1

    float *p_dinv, *p_tmp, *p_h1, *p_h2, *p_tvec;
    cudaGetSymbolAddress((void**)&p_dinv, g_dinv);
    cudaGetSymbolAddress((void**)&p_tmp,  g_tmp);
    cudaGetSymbolAddress((void**)&p_h1,   g_h1);
    cudaGetSymbolAddress((void**)&p_h2,   g_h2);
    cudaGetSymbolAddress((void**)&p_tvec, g_tvec);

    const int T = 256;
    const int nodeBlocks  = (N_NODES + T - 1) / T;
    const int edgeBlocks  = (N_EDGES + T - 1) / T;
    const int vecBlocks   = (N_NODES * (HID / 4) + T - 1) / T;
    const int edgeWarpBlk = (N_EDGES * 32 + T - 1) / T;

    // normalization
    deg_init_kernel<<<nodeBlocks, T>>>(p_dinv);
    deg_count_kernel<<<edgeBlocks, T>>>(dst, p_dinv);
    deg_rsqrt_kernel<<<nodeBlocks, T>>>(p_dinv);

    // text part of the classifier (tiny, once)
    tvec_kernel<<<(OUT_CH + T - 1) / T, T>>>(text, Wc, bc, p_tvec);

    dim3 g1((HID + 127) / 128, (N_NODES + 63) / 64);
    dim3 g3((OUT_CH + 127) / 128, (N_NODES + 63) / 64);

    // ---- layer 1: tmp = x @ W1 ; h1 = selfloop + edges ; +b1, relu ----
    gemm_kernel<64,128,16,4,8,0><<<g1, 256>>>(x, W1, nullptr, p_tmp, N_NODES, IN_CH, HID);
    self_scale_kernel<<<vecBlocks, T>>>((const float4*)p_tmp, p_dinv, (float4*)p_h1);
    edge_agg_kernel<<<edgeWarpBlk, T>>>(src, dst, p_dinv, (const float4*)p_tmp, p_h1);
    bias_act_kernel<true><<<vecBlocks, T>>>((float4*)p_h1, (const float4*)b1);

    // ---- layer 2: tmp = h1 @ W2 ; h2 = selfloop + edges ; +b2 ----
    gemm_kernel<64,128,16,4,8,0><<<g1, 256>>>(p_h1, W2, nullptr, p_tmp, N_NODES, HID, HID);
    self_scale_kernel<<<vecBlocks, T>>>((const float4*)p_tmp, p_dinv, (float4*)p_h2);
    edge_agg_kernel<<<edgeWarpBlk, T>>>(src, dst, p_dinv, (const float4*)p_tmp, p_h2);
    bias_act_kernel<false><<<vecBlocks, T>>>((float4*)p_h2, (const float4*)b2);

    // ---- classifier: out = h2 @ Wc[:HID,:] + tvec ----
    gemm_kernel<64,128,16,4,8,1><<<g3, 256>>>(p_h2, Wc, p_tvec, out, N_NODES, HID, OUT_CH);
}

// round 5
// speedup vs baseline: 1.4498x; 1.4498x over previous
#include <cuda_runtime.h>
#include <cuda_bf16.h>

#define N_NODES 50000
#define IN_CH   256
#define HID     128
#define OUT_CH  1000
#define TEXT_DIM 768
#define N_EDGES 800000

// ---------------- scratch (static device arrays; no allocation APIs) --------
__device__ __align__(16) float g_dinv[N_NODES];
__device__ __align__(16) float g_tmp[N_NODES * HID];
__device__ __align__(16) float g_h1 [N_NODES * HID];
__device__ __align__(16) float g_h2 [N_NODES * HID];
__device__ __align__(16) float g_tvec[OUT_CH];

// ---------------- vector reduction helper -----------------------------------
__device__ __forceinline__ void red_add_v4(float* addr, float a, float b, float c, float d)
{
    asm volatile("red.global.add.v4.f32 [%0], {%1, %2, %3, %4};"
                 :: "l"(addr), "f"(a), "f"(b), "f"(c), "f"(d) : "memory");
}

// ---------------- degree / normalization ------------------------------------
__global__ void deg_init_kernel(float* __restrict__ dinv) {
    int i = blockIdx.x * blockDim.x + threadIdx.x;
    if (i < N_NODES) dinv[i] = 1.0f;              // self-loop contributes 1
}

__global__ void deg_count_kernel(const int* __restrict__ dst,
                                 float* __restrict__ dinv) {
    int e = blockIdx.x * blockDim.x + threadIdx.x;
    if (e < N_EDGES) atomicAdd(&dinv[dst[e]], 1.0f);
}

__global__ void deg_rsqrt_kernel(float* __restrict__ dinv) {
    int i = blockIdx.x * blockDim.x + threadIdx.x;
    if (i < N_NODES) dinv[i] = rsqrtf(dinv[i]);   // deg >= 1 always
}

// ---------------- GEMM A: 64x128 tile, 4x8 microtile (layers 1 & 2) ---------
// Writes C (raw) and C2 = C * dinv[row]^2  (self-loop term, fused epilogue)
template<int BK>
__global__ void __launch_bounds__(256, 2)
gemm_fused_kernel(const float* __restrict__ A, const float* __restrict__ B,
                  const float* __restrict__ dinv,
                  float* __restrict__ C, float* __restrict__ C2,
                  int N, int K, int M)
{
    constexpr int BM = 64, BN = 128, TM = 4, TN = 8;
    __shared__ float As[BM][BK];
    __shared__ float Bs[BK][BN];

    const int tx = threadIdx.x % (BN / TN);
    const int ty = threadIdx.x / (BN / TN);
    const int rowBase = blockIdx.y * BM;
    const int colBase = blockIdx.x * BN;

    float acc[TM][TN];
#pragma unroll
    for (int i = 0; i < TM; i++)
#pragma unroll
        for (int j = 0; j < TN; j++) acc[i][j] = 0.0f;

    for (int k0 = 0; k0 < K; k0 += BK) {
        for (int i = threadIdx.x; i < BM * BK; i += 256) {
            int r = i / BK, c = i % BK;
            int gr = rowBase + r;
            As[r][c] = (gr < N) ? A[gr * K + k0 + c] : 0.0f;
        }
        for (int i = threadIdx.x; i < BK * BN; i += 256) {
            int r = i / BN, c = i % BN;
            Bs[r][c] = B[(k0 + r) * M + colBase + c];
        }
        __syncthreads();

#pragma unroll
        for (int k = 0; k < BK; k++) {
            float a[TM], b[TN];
#pragma unroll
            for (int i = 0; i < TM; i++) a[i] = As[ty * TM + i][k];
#pragma unroll
            for (int j = 0; j < TN; j++) b[j] = Bs[k][tx * TN + j];
#pragma unroll
            for (int i = 0; i < TM; i++)
#pragma unroll
                for (int j = 0; j < TN; j++) acc[i][j] += a[i] * b[j];
        }
        __syncthreads();
    }

#pragma unroll
    for (int i = 0; i < TM; i++) {
        int gr = rowBase + ty * TM + i;
        if (gr >= N) continue;
        float w = dinv[gr]; w = w * w;
#pragma unroll
        for (int j = 0; j < TN; j++) {
            int gc = colBase + tx * TN + j;
            float v = acc[i][j];
            C [gr * M + gc] = v;
            C2[gr * M + gc] = v * w;
        }
    }
}

// ---------------- GEMM B: 128x128 tile, 8x8 microtile (classifier) ----------
// C = A @ B + addvec[col]
__global__ void __launch_bounds__(256, 2)
gemm_big_kernel(const float* __restrict__ A, const float* __restrict__ B,
                const float* __restrict__ addvec, float* __restrict__ C,
                int N, int K, int M)
{
    constexpr int BM = 128, BN = 128, BK = 16, TM = 8, TN = 8;
    __shared__ float As[BM][BK];
    __shared__ float Bs[BK][BN];

    const int tx = threadIdx.x % (BN / TN);   // 0..15
    const int ty = threadIdx.x / (BN / TN);   // 0..15
    const int rowBase = blockIdx.y * BM;
    const int colBase = blockIdx.x * BN;

    float acc[TM][TN];
#pragma unroll
    for (int i = 0; i < TM; i++)
#pragma unroll
        for (int j = 0; j < TN; j++) acc[i][j] = 0.0f;

    for (int k0 = 0; k0 < K; k0 += BK) {
        for (int i = threadIdx.x; i < BM * BK; i += 256) {
            int r = i / BK, c = i % BK;
            int gr = rowBase + r;
            As[r][c] = (gr < N) ? A[gr * K + k0 + c] : 0.0f;
        }
        for (int i = threadIdx.x; i < BK * BN; i += 256) {
            int r = i / BN, c = i % BN;
            int gc = colBase + c;
            Bs[r][c] = (gc < M) ? B[(k0 + r) * M + gc] : 0.0f;
        }
        __syncthreads();

#pragma unroll
        for (int k = 0; k < BK; k++) {
            float a[TM], b[TN];
#pragma unroll
            for (int i = 0; i < TM; i++) a[i] = As[ty * TM + i][k];
#pragma unroll
            for (int j = 0; j < TN; j++) b[j] = Bs[k][tx * TN + j];
#pragma unroll
            for (int i = 0; i < TM; i++)
#pragma unroll
                for (int j = 0; j < TN; j++) acc[i][j] += a[i] * b[j];
        }
        __syncthreads();
    }

#pragma unroll
    for (int i = 0; i < TM; i++) {
        int gr = rowBase + ty * TM + i;
        if (gr >= N) continue;
#pragma unroll
        for (int j = 0; j < TN; j++) {
            int gc = colBase + tx * TN + j;
            if (gc < M) C[gr * M + gc] = acc[i][j] + addvec[gc];
        }
    }
}

// ---------------- edge aggregation: one warp per edge, vector RED -----------
__global__ void edge_agg_kernel(const int* __restrict__ src,
                                const int* __restrict__ dst,
                                const float* __restrict__ dinv,
                                const float4* __restrict__ h,
                                float* __restrict__ outp)
{
    int gid  = blockIdx.x * blockDim.x + threadIdx.x;
    int warp = gid >> 5;
    int lane = gid & 31;
    if (warp >= N_EDGES) return;
    int s = __ldg(&src[warp]);
    int d = __ldg(&dst[warp]);
    float w = dinv[s] * dinv[d];
    float4 v = h[s * (HID / 4) + lane];
    float* o = outp + d * HID + lane * 4;
    red_add_v4(o, v.x * w, v.y * w, v.z * w, v.w * w);
}

// ---------------- bias (+optional relu), in place ---------------------------
template<bool RELU>
__global__ void bias_act_kernel(float4* __restrict__ h, const float4* __restrict__ bias)
{
    int gid = blockIdx.x * blockDim.x + threadIdx.x;
    if (gid >= N_NODES * (HID / 4)) return;
    float4 v = h[gid];
    float4 b = bias[gid & ((HID / 4) - 1)];
    v.x += b.x; v.y += b.y; v.z += b.z; v.w += b.w;
    if (RELU) {
        v.x = fmaxf(v.x, 0.f); v.y = fmaxf(v.y, 0.f);
        v.z = fmaxf(v.z, 0.f); v.w = fmaxf(v.w, 0.f);
    }
    h[gid] = v;
}

// ---------------- tvec: text_vec @ Wc[HID:,:] + bc, k-split -----------------
__global__ void tvec_init_kernel(const float* __restrict__ bc, float* __restrict__ tvec)
{
    int j = blockIdx.x * blockDim.x + threadIdx.x;
    if (j < OUT_CH) tvec[j] = bc[j];
}

// grid (8, 12): x covers 8*128=1024 >= OUT_CH cols, y covers 12*64=768 k's
__global__ void tvec_partial_kernel(const float* __restrict__ text,
                                    const float* __restrict__ Wc,
                                    float* __restrict__ tvec)
{
    int j  = blockIdx.x * blockDim.x + threadIdx.x;
    int k0 = blockIdx.y * 64;
    if (j >= OUT_CH) return;
    float acc = 0.0f;
#pragma unroll 8
    for (int k = 0; k < 64; k++)
        acc += __ldg(&text[k0 + k]) * __ldg(&Wc[(HID + k0 + k) * OUT_CH + j]);
    atomicAdd(&tvec[j], acc);
}

// ---------------------------------------------------------------------------
extern "C" void kernel_launch(void* const* d_in, const int* in_sizes, int n_in,
                              void* d_out, int out_size)
{
    const float* x    = (const float*)d_in[0];
    const int*   ei   = (const int*)d_in[1];       // [2, E] int32
    const float* text = (const float*)d_in[2];
    const float* W1   = (const float*)d_in[3];
    const float* b1   = (const float*)d_in[4];
    const float* W2   = (const float*)d_in[5];
    const float* b2   = (const float*)d_in[6];
    const float* Wc   = (const float*)d_in[7];
    const float* bc   = (const float*)d_in[8];
    float*       out  = (float*)d_out;

    const int* src = ei;                 // row 0
    const int* dst = ei + N_EDGES;       // row 1

    float *p_dinv, *p_tmp, *p_h1, *p_h2, *p_tvec;
    cudaGetSymbolAddress((void**)&p_dinv, g_dinv);
    cudaGetSymbolAddress((void**)&p_tmp,  g_tmp);
    cudaGetSymbolAddress((void**)&p_h1,   g_h1);
    cudaGetSymbolAddress((void**)&p_h2,   g_h2);
    cudaGetSymbolAddress((void**)&p_tvec, g_tvec);

    const int T = 256;
    const int nodeBlocks  = (N_NODES + T - 1) / T;
    const int edgeBlocks  = (N_EDGES + T - 1) / T;
    const int vecBlocks   = (N_NODES * (HID / 4) + T - 1) / T;
    const int edgeWarpBlk = (N_EDGES * 32 + T - 1) / T;

    // normalization
    deg_init_kernel<<<nodeBlocks, T>>>(p_dinv);
    deg_count_kernel<<<edgeBlocks, T>>>(dst, p_dinv);
    deg_rsqrt_kernel<<<nodeBlocks, T>>>(p_dinv);

    // text part of the classifier (tiny), k-split for parallelism
    tvec_init_kernel<<<(OUT_CH + 127) / 128, 128>>>(bc, p_tvec);
    tvec_partial_kernel<<<dim3(8, 12), 128>>>(text, Wc, p_tvec);

    dim3 g1(1, (N_NODES + 63) / 64);                       // M=128 fits one BN
    dim3 g3((OUT_CH + 127) / 128, (N_NODES + 127) / 128);

    // ---- layer 1: tmp = x @ W1 (+fused self-loop into h1); edges; +b1,relu -
    gemm_fused_kernel<16><<<g1, 256>>>(x, W1, p_dinv, p_tmp, p_h1, N_NODES, IN_CH, HID);
    edge_agg_kernel<<<edgeWarpBlk, T>>>(src, dst, p_dinv, (const float4*)p_tmp, p_h1);
    bias_act_kernel<true><<<vecBlocks, T>>>((float4*)p_h1, (const float4*)b1);

    // ---- layer 2 ----
    gemm_fused_kernel<16><<<g1, 256>>>(p_h1, W2, p_dinv, p_tmp, p_h2, N_NODES, HID, HID);
    edge_agg_kernel<<<edgeWarpBlk, T>>>(src, dst, p_dinv, (const float4*)p_tmp, p_h2);
    bias_act_kernel<false><<<vecBlocks, T>>>((float4*)p_h2, (const float4*)b2);

    // ---- classifier: out = h2 @ Wc[:HID,:] + tvec ----
    gemm_big_kernel<<<g3, 256>>>(p_h2, Wc, p_tvec, out, N_NODES, HID, OUT_CH);
}

// round 7
// speedup vs baseline: 1.4519x; 1.0014x over previous
#include <cuda_runtime.h>
#include <cuda_bf16.h>

#define N_NODES 50000
#define IN_CH   256
#define HID     128
#define OUT_CH  1000
#define TEXT_DIM 768
#define N_EDGES 800000

// ---------------- scratch (static device arrays; no allocation APIs) --------
__device__ __align__(16) float g_dinv[N_NODES];
__device__ __align__(16) float g_tmp[N_NODES * HID];
__device__ __align__(16) float g_h1 [N_NODES * HID];
__device__ __align__(16) float g_h2 [N_NODES * HID];
__device__ __align__(16) float g_tvec[OUT_CH];

// ---------------- vector reduction helper -----------------------------------
__device__ __forceinline__ void red_add_v4(float* addr, float a, float b, float c, float d)
{
    asm volatile("red.global.add.v4.f32 [%0], {%1, %2, %3, %4};"
                 :: "l"(addr), "f"(a), "f"(b), "f"(c), "f"(d) : "memory");
}

// ---------------- degree / normalization ------------------------------------
__global__ void deg_init_kernel(float* __restrict__ dinv) {
    int i = blockIdx.x * blockDim.x + threadIdx.x;
    if (i < N_NODES) dinv[i] = 1.0f;              // self-loop contributes 1
}

__global__ void deg_count_kernel(const int* __restrict__ dst,
                                 float* __restrict__ dinv) {
    int e = blockIdx.x * blockDim.x + threadIdx.x;
    if (e < N_EDGES) atomicAdd(&dinv[dst[e]], 1.0f);
}

__global__ void deg_rsqrt_kernel(float* __restrict__ dinv) {
    int i = blockIdx.x * blockDim.x + threadIdx.x;
    if (i < N_NODES) dinv[i] = rsqrtf(dinv[i]);   // deg >= 1 always
}

// ---------------- GEMM A: 64x128 tile, 4x8 microtile (layers 1 & 2) ---------
// Writes C (raw) and C2 = C * dinv[row]^2  (self-loop term, fused epilogue)
template<int BK>
__global__ void __launch_bounds__(256, 2)
gemm_fused_kernel(const float* __restrict__ A, const float* __restrict__ B,
                  const float* __restrict__ dinv,
                  float* __restrict__ C, float* __restrict__ C2,
                  int N, int K, int M)
{
    constexpr int BM = 64, BN = 128, TM = 4, TN = 8;
    __shared__ float As[BM][BK];
    __shared__ float Bs[BK][BN];

    const int tx = threadIdx.x % (BN / TN);
    const int ty = threadIdx.x / (BN / TN);
    const int rowBase = blockIdx.y * BM;
    const int colBase = blockIdx.x * BN;

    float acc[TM][TN];
#pragma unroll
    for (int i = 0; i < TM; i++)
#pragma unroll
        for (int j = 0; j < TN; j++) acc[i][j] = 0.0f;

    for (int k0 = 0; k0 < K; k0 += BK) {
        for (int i = threadIdx.x; i < BM * BK; i += 256) {
            int r = i / BK, c = i % BK;
            int gr = rowBase + r;
            As[r][c] = (gr < N) ? A[gr * K + k0 + c] : 0.0f;
        }
        for (int i = threadIdx.x; i < BK * BN; i += 256) {
            int r = i / BN, c = i % BN;
            Bs[r][c] = B[(k0 + r) * M + colBase + c];
        }
        __syncthreads();

#pragma unroll
        for (int k = 0; k < BK; k++) {
            float a[TM], b[TN];
#pragma unroll
            for (int i = 0; i < TM; i++) a[i] = As[ty * TM + i][k];
#pragma unroll
            for (int j = 0; j < TN; j++) b[j] = Bs[k][tx * TN + j];
#pragma unroll
            for (int i = 0; i < TM; i++)
#pragma unroll
                for (int j = 0; j < TN; j++) acc[i][j] += a[i] * b[j];
        }
        __syncthreads();
    }

#pragma unroll
    for (int i = 0; i < TM; i++) {
        int gr = rowBase + ty * TM + i;
        if (gr >= N) continue;
        float w = dinv[gr]; w = w * w;
#pragma unroll
        for (int j = 0; j < TN; j++) {
            int gc = colBase + tx * TN + j;
            float v = acc[i][j];
            C [gr * M + gc] = v;
            C2[gr * M + gc] = v * w;
        }
    }
}

// ---------------- GEMM B: 128x128 tile, 8x8 microtile (classifier) ----------
// C = A @ B + addvec[col]
__global__ void __launch_bounds__(256, 2)
gemm_big_kernel(const float* __restrict__ A, const float* __restrict__ B,
                const float* __restrict__ addvec, float* __restrict__ C,
                int N, int K, int M)
{
    constexpr int BM = 128, BN = 128, BK = 16, TM = 8, TN = 8;
    __shared__ float As[BM][BK];
    __shared__ float Bs[BK][BN];

    const int tx = threadIdx.x % (BN / TN);   // 0..15
    const int ty = threadIdx.x / (BN / TN);   // 0..15
    const int rowBase = blockIdx.y * BM;
    const int colBase = blockIdx.x * BN;

    float acc[TM][TN];
#pragma unroll
    for (int i = 0; i < TM; i++)
#pragma unroll
        for (int j = 0; j < TN; j++) acc[i][j] = 0.0f;

    for (int k0 = 0; k0 < K; k0 += BK) {
        for (int i = threadIdx.x; i < BM * BK; i += 256) {
            int r = i / BK, c = i % BK;
            int gr = rowBase + r;
            As[r][c] = (gr < N) ? A[gr * K + k0 + c] : 0.0f;
        }
        for (int i = threadIdx.x; i < BK * BN; i += 256) {
            int r = i / BN, c = i % BN;
            int gc = colBase + c;
            Bs[r][c] = (gc < M) ? B[(k0 + r) * M + gc] : 0.0f;
        }
        __syncthreads();

#pragma unroll
        for (int k = 0; k < BK; k++) {
            float a[TM], b[TN];
#pragma unroll
            for (int i = 0; i < TM; i++) a[i] = As[ty * TM + i][k];
#pragma unroll
            for (int j = 0; j < TN; j++) b[j] = Bs[k][tx * TN + j];
#pragma unroll
            for (int i = 0; i < TM; i++)
#pragma unroll
                for (int j = 0; j < TN; j++) acc[i][j] += a[i] * b[j];
        }
        __syncthreads();
    }

#pragma unroll
    for (int i = 0; i < TM; i++) {
        int gr = rowBase + ty * TM + i;
        if (gr >= N) continue;
#pragma unroll
        for (int j = 0; j < TN; j++) {
            int gc = colBase + tx * TN + j;
            if (gc < M) C[gr * M + gc] = acc[i][j] + addvec[gc];
        }
    }
}

// ---------------- edge aggregation: one warp per edge, vector RED -----------
__global__ void edge_agg_kernel(const int* __restrict__ src,
                                const int* __restrict__ dst,
                                const float* __restrict__ dinv,
                                const float4* __restrict__ h,
                                float* __restrict__ outp)
{
    int gid  = blockIdx.x * blockDim.x + threadIdx.x;
    int warp = gid >> 5;
    int lane = gid & 31;
    if (warp >= N_EDGES) return;
    int s = __ldg(&src[warp]);
    int d = __ldg(&dst[warp]);
    float w = dinv[s] * dinv[d];
    float4 v = h[s * (HID / 4) + lane];
    float* o = outp + d * HID + lane * 4;
    red_add_v4(o, v.x * w, v.y * w, v.z * w, v.w * w);
}

// ---------------- bias (+optional relu), in place ---------------------------
template<bool RELU>
__global__ void bias_act_kernel(float4* __restrict__ h, const float4* __restrict__ bias)
{
    int gid = blockIdx.x * blockDim.x + threadIdx.x;
    if (gid >= N_NODES * (HID / 4)) return;
    float4 v = h[gid];
    float4 b = bias[gid & ((HID / 4) - 1)];
    v.x += b.x; v.y += b.y; v.z += b.z; v.w += b.w;
    if (RELU) {
        v.x = fmaxf(v.x, 0.f); v.y = fmaxf(v.y, 0.f);
        v.z = fmaxf(v.z, 0.f); v.w = fmaxf(v.w, 0.f);
    }
    h[gid] = v;
}

// ---------------- tvec: text_vec @ Wc[HID:,:] + bc, k-split -----------------
__global__ void tvec_init_kernel(const float* __restrict__ bc, float* __restrict__ tvec)
{
    int j = blockIdx.x * blockDim.x + threadIdx.x;
    if (j < OUT_CH) tvec[j] = bc[j];
}

// grid (8, 12): x covers 8*128=1024 >= OUT_CH cols, y covers 12*64=768 k's
__global__ void tvec_partial_kernel(const float* __restrict__ text,
                                    const float* __restrict__ Wc,
                                    float* __restrict__ tvec)
{
    int j  = blockIdx.x * blockDim.x + threadIdx.x;
    int k0 = blockIdx.y * 64;
    if (j >= OUT_CH) return;
    float acc = 0.0f;
#pragma unroll 8
    for (int k = 0; k < 64; k++)
        acc += __ldg(&text[k0 + k]) * __ldg(&Wc[(HID + k0 + k) * OUT_CH + j]);
    atomicAdd(&tvec[j], acc);
}

// ---------------------------------------------------------------------------
extern "C" void kernel_launch(void* const* d_in, const int* in_sizes, int n_in,
                              void* d_out, int out_size)
{
    const float* x    = (const float*)d_in[0];
    const int*   ei   = (const int*)d_in[1];       // [2, E] int32
    const float* text = (const float*)d_in[2];
    const float* W1   = (const float*)d_in[3];
    const float* b1   = (const float*)d_in[4];
    const float* W2   = (const float*)d_in[5];
    const float* b2   = (const float*)d_in[6];
    const float* Wc   = (const float*)d_in[7];
    const float* bc   = (const float*)d_in[8];
    float*       out  = (float*)d_out;

    const int* src = ei;                 // row 0
    const int* dst = ei + N_EDGES;       // row 1

    float *p_dinv, *p_tmp, *p_h1, *p_h2, *p_tvec;
    cudaGetSymbolAddress((void**)&p_dinv, g_dinv);
    cudaGetSymbolAddress((void**)&p_tmp,  g_tmp);
    cudaGetSymbolAddress((void**)&p_h1,   g_h1);
    cudaGetSymbolAddress((void**)&p_h2,   g_h2);
    cudaGetSymbolAddress((void**)&p_tvec, g_tvec);

    const int T = 256;
    const int nodeBlocks  = (N_NODES + T - 1) / T;
    const int edgeBlocks  = (N_EDGES + T - 1) / T;
    const int vecBlocks   = (N_NODES * (HID / 4) + T - 1) / T;
    const int edgeWarpBlk = (N_EDGES * 32 + T - 1) / T;

    // normalization
    deg_init_kernel<<<nodeBlocks, T>>>(p_dinv);
    deg_count_kernel<<<edgeBlocks, T>>>(dst, p_dinv);
    deg_rsqrt_kernel<<<nodeBlocks, T>>>(p_dinv);

    // text part of the classifier (tiny), k-split for parallelism
    tvec_init_kernel<<<(OUT_CH + 127) / 128, 128>>>(bc, p_tvec);
    tvec_partial_kernel<<<dim3(8, 12), 128>>>(text, Wc, p_tvec);

    dim3 g1(1, (N_NODES + 63) / 64);                       // M=128 fits one BN
    dim3 g3((OUT_CH + 127) / 128, (N_NODES + 127) / 128);

    // ---- layer 1: tmp = x @ W1 (+fused self-loop into h1); edges; +b1,relu -
    gemm_fused_kernel<16><<<g1, 256>>>(x, W1, p_dinv, p_tmp, p_h1, N_NODES, IN_CH, HID);
    edge_agg_kernel<<<edgeWarpBlk, T>>>(src, dst, p_dinv, (const float4*)p_tmp, p_h1);
    bias_act_kernel<true><<<vecBlocks, T>>>((float4*)p_h1, (const float4*)b1);

    // ---- layer 2 ----
    gemm_fused_kernel<16><<<g1, 256>>>(p_h1, W2, p_dinv, p_tmp, p_h2, N_NODES, HID, HID);
    edge_agg_kernel<<<edgeWarpBlk, T>>>(src, dst, p_dinv, (const float4*)p_tmp, p_h2);
    bias_act_kernel<false><<<vecBlocks, T>>>((float4*)p_h2, (const float4*)b2);

    // ---- classifier: out = h2 @ Wc[:HID,:] + tvec ----
    gemm_big_kernel<<<g3, 256>>>(p_h2, Wc, p_tvec, out, N_NODES, HID, OUT_CH);
}